// round 14
// baseline (speedup 1.0000x reference)
#include <cuda_runtime.h>
#include <math_constants.h>

#define B_ 8
#define L_ 2000
#define C_ 256
#define N_ (B_ * C_)            // 2048
#define A10_OFF 4096000ull      // res elements
#define A20_OFF 86016000ull     // res + attn10 elements

// Scratch (allocation-free rule: __device__ globals)
__device__ float g_xT[N_ * L_];    // (B, C, L) == (n, L)
__device__ float g_resT[N_ * L_];  // (n, L)

// ---- packed f32x2 helpers (sm_103a FFMA2) ----
static __device__ __forceinline__ unsigned long long fma2(unsigned long long a,
                                                          unsigned long long b,
                                                          unsigned long long c) {
    unsigned long long d;
    asm("fma.rn.f32x2 %0, %1, %2, %3;" : "=l"(d) : "l"(a), "l"(b), "l"(c));
    return d;
}
static __device__ __forceinline__ float2 unpack2(unsigned long long v) {
    float lo, hi;
    asm("mov.b64 {%0, %1}, %2;" : "=f"(lo), "=f"(hi) : "l"(v));
    return make_float2(lo, hi);
}
static __device__ __forceinline__ float ex2(float x) {
    float r;
    asm("ex2.approx.f32 %0, %1;" : "=f"(r) : "f"(x));
    return r;
}
static __device__ __forceinline__ float warp_sum(float v) {
#pragma unroll
    for (int off = 16; off; off >>= 1) v += __shfl_xor_sync(0xffffffffu, v, off);
    return v;
}
static __device__ __forceinline__ float frcp(float x) {
    float r;
    asm("rcp.approx.f32 %0, %1;" : "=f"(r) : "f"(x));
    return r;
}

// ---------------- Kernel A: x (B,L,C) -> xT (B,C,L) ----------------
__global__ void k_transpose_x(const float* __restrict__ x) {
    __shared__ float tile[32][33];
    int b = blockIdx.z;
    int l0 = blockIdx.x * 32, c0 = blockIdx.y * 32;
    int tx = threadIdx.x, ty = threadIdx.y;
#pragma unroll
    for (int j = 0; j < 32; j += 8) {
        int l = l0 + ty + j;
        if (l < L_) tile[ty + j][tx] = x[((size_t)b * L_ + l) * C_ + (c0 + tx)];
    }
    __syncthreads();
#pragma unroll
    for (int j = 0; j < 32; j += 8) {
        int c = c0 + ty + j;
        int l = l0 + tx;
        if (l < L_) g_xT[((size_t)b * C_ + c) * L_ + l] = tile[tx][ty + j];
    }
}

// ---------------- Kernel D: resT (B,C,L) -> out res region (B,L,C) ----------------
__global__ void k_transpose_res(float* __restrict__ out) {
    __shared__ float tile[32][33];
    int b = blockIdx.z;
    int l0 = blockIdx.x * 32, c0 = blockIdx.y * 32;
    int tx = threadIdx.x, ty = threadIdx.y;
#pragma unroll
    for (int j = 0; j < 32; j += 8) {
        int c = c0 + ty + j;
        int l = l0 + tx;
        if (l < L_) tile[ty + j][tx] = g_resT[((size_t)b * C_ + c) * L_ + l];
    }
    __syncthreads();
#pragma unroll
    for (int j = 0; j < 32; j += 8) {
        int l = l0 + ty + j;
        int c = c0 + tx;
        if (l < L_) out[((size_t)b * L_ + l) * C_ + c] = tile[tx][ty + j];
    }
}

// ---------------- Kernel B: both branches, bx&1 selects; n = bx>>1 ----------------
__global__ __launch_bounds__(256, 2) void k_branches(
    const float* __restrict__ wq10, const float* __restrict__ bq10,
    const float* __restrict__ wk10, const float* __restrict__ bk10,
    const float* __restrict__ wl10, const float* __restrict__ bl10,
    const float* __restrict__ wq20, const float* __restrict__ bq20,
    const float* __restrict__ wk20, const float* __restrict__ bk20,
    const float* __restrict__ wl20, const float* __restrict__ bl20,
    float* __restrict__ out)
{
    int bx = blockIdx.x;
    int n = bx >> 1;
    int tid = threadIdx.x, lane = tid & 31, wid = tid >> 5;

    __shared__ float zs[L_];
    __shared__ float2 qb2[L_];     // q duplicated into both halves, pre-scaled by s*log2e
    __shared__ float kb[L_];
    __shared__ float wbuf[1300];   // branch-dependent weight staging
    __shared__ float bbuf[72];

    for (int i = tid; i < L_; i += 256) zs[i] = g_xT[(size_t)n * L_ + i];

    if ((bx & 1) == 0) {
        // =================== p = 10 branch ===================
        float* wqs = wbuf;          // 100
        float* wks = wbuf + 100;    // 100
        float* bqs = bbuf;          // 10
        float* bks = bbuf + 10;     // 10
        if (tid < 100) { wqs[tid] = wq10[tid]; wks[tid] = wk10[tid]; }
        if (tid >= 128 && tid < 138) {
            bqs[tid - 128] = bq10[tid - 128];
            bks[tid - 128] = bk10[tid - 128];
        }
        __syncthreads();

        const float s10 = rsqrtf(10.0f) * (float)M_LOG2E;   // fold log2e for ex2
        for (int e = tid; e < L_; e += 256) {
            int wi = e / 10, pi = e - wi * 10;
            unsigned long long aq = 0ull, ak = 0ull;
#pragma unroll
            for (int j = 0; j < 5; j++) {
                unsigned long long zz = *(const unsigned long long*)&zs[wi * 10 + 2 * j];
                aq = fma2(zz, *(const unsigned long long*)&wqs[pi * 10 + 2 * j], aq);
                ak = fma2(zz, *(const unsigned long long*)&wks[pi * 10 + 2 * j], ak);
            }
            float2 q2 = unpack2(aq), k2 = unpack2(ak);
            float qv = (bqs[pi] + q2.x + q2.y) * s10;
            qb2[e] = make_float2(qv, qv);
            kb[pi * 200 + wi] = bks[pi] + k2.x + k2.y;
        }
        __syncthreads();

        // ---- scores: kv register-resident; each warp owns a column slice, loops rows ----
        float* attn = out + A10_OFF + (size_t)n * 40000;
        const bool act = (lane < 25);           // 25 lanes x 8 cols = 200
        const int c0 = act ? 8 * lane : 0;
        unsigned long long kvr[10][4];
#pragma unroll
        for (int pi = 0; pi < 10; pi++) {
            ulonglong2 a = *(const ulonglong2*)&kb[pi * 200 + c0];
            ulonglong2 b = *(const ulonglong2*)&kb[pi * 200 + c0 + 4];
            kvr[pi][0] = a.x; kvr[pi][1] = a.y; kvr[pi][2] = b.x; kvr[pi][3] = b.y;
        }
        for (int r = wid; r < 200; r += 8) {
            unsigned long long acc[4] = {0ull, 0ull, 0ull, 0ull};
#pragma unroll
            for (int pi = 0; pi < 10; pi++) {
                unsigned long long qq = *(const unsigned long long*)&qb2[r * 10 + pi];
#pragma unroll
                for (int j = 0; j < 4; j++) acc[j] = fma2(qq, kvr[pi][j], acc[j]);
            }
            float2 v[4];
            float part = 0.f;
#pragma unroll
            for (int j = 0; j < 4; j++) {
                v[j] = unpack2(acc[j]);
                v[j].x = ex2(v[j].x);
                v[j].y = ex2(v[j].y);
                part += v[j].x + v[j].y;
            }
            if (!act) part = 0.f;
            float inv = frcp(warp_sum(part));
            if (act) {
                float4 s0 = make_float4(v[0].x * inv, v[0].y * inv, v[1].x * inv, v[1].y * inv);
                float4 s1 = make_float4(v[2].x * inv, v[2].y * inv, v[3].x * inv, v[3].y * inv);
                __stcs((float4*)&attn[(size_t)r * 200 + c0], s0);
                __stcs((float4*)&attn[(size_t)r * 200 + c0 + 4], s1);
            }
        }
    } else {
        // =================== p = 20 branch + res ===================
        float* wqs   = wbuf;           // 400
        float* wks   = wbuf + 400;     // 400
        float* wl20s = wbuf + 800;     // 400 (interp-folded)
        float* wl10s = wbuf + 1200;    // 100 (interp-folded)
        float* bqs   = bbuf;           // 20
        float* bks   = bbuf + 20;      // 20
        float* bl20s = bbuf + 40;      // 20
        float* bl10s = bbuf + 60;      // 10
        if (tid < 100) {
            int r = tid / 10, j = tid - r * 10;
            wl10s[tid] = 0.25f * (wl10[(20 * r + 9) * 10 + j] + wl10[(20 * r + 10) * 10 + j]);
        }
        for (int t = tid; t < 400; t += 256) {
            wqs[t] = wq20[t]; wks[t] = wk20[t];
            int r = t / 20, j = t - r * 20;
            wl20s[t] = 0.5f * wl20[(5 * r + 2) * 20 + j];
        }
        if (tid >= 128 && tid < 148) {
            int u = tid - 128;
            bqs[u] = bq20[u]; bks[u] = bk20[u];
            bl20s[u] = 0.5f * bl20[5 * u + 2];
            if (u < 10) bl10s[u] = 0.25f * (bl10[20 * u + 9] + bl10[20 * u + 10]);
        }
        __syncthreads();

        const float s20 = rsqrtf(20.0f) * (float)M_LOG2E;
        for (int e = tid; e < L_; e += 256) {
            int wi = e / 20, pi = e - wi * 20;
            unsigned long long aq = 0ull, ak = 0ull;
#pragma unroll
            for (int j = 0; j < 10; j++) {
                unsigned long long zz = *(const unsigned long long*)&zs[wi * 20 + 2 * j];
                aq = fma2(zz, *(const unsigned long long*)&wqs[pi * 20 + 2 * j], aq);
                ak = fma2(zz, *(const unsigned long long*)&wks[pi * 20 + 2 * j], ak);
            }
            float2 q2 = unpack2(aq), k2 = unpack2(ak);
            float qv = (bqs[pi] + q2.x + q2.y) * s20;
            qb2[e] = make_float2(qv, qv);
            kb[pi * 100 + wi] = bks[pi] + k2.x + k2.y;
        }

        // res = folded z2(p10) + folded z2(p20), written transposed
        for (int i = tid; i < L_; i += 256) {
            int a1i = i / 10, r1 = i - a1i * 10;
            unsigned long long acc1 = 0ull;
#pragma unroll
            for (int j = 0; j < 5; j++) {
                unsigned long long zz = *(const unsigned long long*)&zs[a1i * 10 + 2 * j];
                acc1 = fma2(zz, *(const unsigned long long*)&wl10s[r1 * 10 + 2 * j], acc1);
            }
            int a2i = i / 20, r2 = i - a2i * 20;
            unsigned long long acc2 = 0ull;
#pragma unroll
            for (int j = 0; j < 10; j++) {
                unsigned long long zz = *(const unsigned long long*)&zs[a2i * 20 + 2 * j];
                acc2 = fma2(zz, *(const unsigned long long*)&wl20s[r2 * 20 + 2 * j], acc2);
            }
            float2 u1 = unpack2(acc1), u2 = unpack2(acc2);
            g_resT[(size_t)n * L_ + i] = bl10s[r1] + bl20s[r2] + u1.x + u1.y + u2.x + u2.y;
        }
        __syncthreads();

        // ---- scores: kv register-resident; each warp owns a column slice, loops rows ----
        float* attn = out + A20_OFF + (size_t)n * 10000;
        const bool act = (lane < 25);           // 25 lanes x 4 cols = 100
        const int c0 = act ? 4 * lane : 0;
        unsigned long long kvr[20][2];
#pragma unroll
        for (int pi = 0; pi < 20; pi++) {
            ulonglong2 a = *(const ulonglong2*)&kb[pi * 100 + c0];
            kvr[pi][0] = a.x; kvr[pi][1] = a.y;
        }
        for (int r = wid; r < 100; r += 8) {
            unsigned long long acc[2] = {0ull, 0ull};
#pragma unroll
            for (int pi = 0; pi < 20; pi++) {
                unsigned long long qq = *(const unsigned long long*)&qb2[r * 20 + pi];
                acc[0] = fma2(qq, kvr[pi][0], acc[0]);
                acc[1] = fma2(qq, kvr[pi][1], acc[1]);
            }
            float2 v0 = unpack2(acc[0]), v1 = unpack2(acc[1]);
            v0.x = ex2(v0.x); v0.y = ex2(v0.y);
            v1.x = ex2(v1.x); v1.y = ex2(v1.y);
            float part = act ? (v0.x + v0.y + v1.x + v1.y) : 0.f;
            float inv = frcp(warp_sum(part));
            if (act) {
                float4 s = make_float4(v0.x * inv, v0.y * inv, v1.x * inv, v1.y * inv);
                __stcs((float4*)&attn[(size_t)r * 100 + c0], s);
            }
        }
    }
}

extern "C" void kernel_launch(void* const* d_in, const int* in_sizes, int n_in,
                              void* d_out, int out_size) {
    const float* x    = (const float*)d_in[0];
    const float* wq10 = (const float*)d_in[1];
    const float* bq10 = (const float*)d_in[2];
    const float* wk10 = (const float*)d_in[3];
    const float* bk10 = (const float*)d_in[4];
    const float* wl10 = (const float*)d_in[5];
    const float* bl10 = (const float*)d_in[6];
    const float* wq20 = (const float*)d_in[7];
    const float* bq20 = (const float*)d_in[8];
    const float* wk20 = (const float*)d_in[9];
    const float* bk20 = (const float*)d_in[10];
    const float* wl20 = (const float*)d_in[11];
    const float* bl20 = (const float*)d_in[12];
    float* out = (float*)d_out;

    dim3 tb(32, 8);
    dim3 gt((L_ + 31) / 32, C_ / 32, B_);
    k_transpose_x<<<gt, tb>>>(x);
    k_branches<<<2 * N_, 256>>>(wq10, bq10, wk10, bk10, wl10, bl10,
                                wq20, bq20, wk20, bk20, wl20, bl20, out);
    k_transpose_res<<<gt, tb>>>(out);
}

// round 15
// speedup vs baseline: 1.1388x; 1.1388x over previous
#include <cuda_runtime.h>
#include <math_constants.h>

#define B_ 8
#define L_ 2000
#define C_ 256
#define N_ (B_ * C_)            // 2048
#define A10_OFF 4096000ull      // res elements
#define A20_OFF 86016000ull     // res + attn10 elements

// Scratch (allocation-free rule: __device__ globals)
__device__ float g_xT[N_ * L_];    // (B, C, L) == (n, L)
__device__ float g_resT[N_ * L_];  // (n, L)

// ---- packed f32x2 helpers (sm_103a FFMA2) ----
static __device__ __forceinline__ unsigned long long fma2(unsigned long long a,
                                                          unsigned long long b,
                                                          unsigned long long c) {
    unsigned long long d;
    asm("fma.rn.f32x2 %0, %1, %2, %3;" : "=l"(d) : "l"(a), "l"(b), "l"(c));
    return d;
}
static __device__ __forceinline__ float2 unpack2(unsigned long long v) {
    float lo, hi;
    asm("mov.b64 {%0, %1}, %2;" : "=f"(lo), "=f"(hi) : "l"(v));
    return make_float2(lo, hi);
}
static __device__ __forceinline__ float ex2(float x) {
    float r;
    asm("ex2.approx.f32 %0, %1;" : "=f"(r) : "f"(x));
    return r;
}
static __device__ __forceinline__ float warp_sum(float v) {
#pragma unroll
    for (int off = 16; off; off >>= 1) v += __shfl_xor_sync(0xffffffffu, v, off);
    return v;
}
static __device__ __forceinline__ float frcp(float x) {
    float r;
    asm("rcp.approx.f32 %0, %1;" : "=f"(r) : "f"(x));
    return r;
}

// ---------------- Kernel A: x (B,L,C) -> xT (B,C,L), 128-bit both sides ----------------
// block (8,32): tx indexes 4-float chunks, ty indexes rows of the 32x32 tile
__global__ void k_transpose_x(const float* __restrict__ x) {
    __shared__ float tile[32][33];
    int b = blockIdx.z;
    int l0 = blockIdx.x * 32, c0 = blockIdx.y * 32;
    int tx = threadIdx.x, ty = threadIdx.y;
    // load: rows = l, 128-bit along C
    {
        int l = l0 + ty;
        if (l < L_) {
            float4 v = *(const float4*)&x[((size_t)b * L_ + l) * C_ + c0 + 4 * tx];
            tile[ty][4 * tx + 0] = v.x;
            tile[ty][4 * tx + 1] = v.y;
            tile[ty][4 * tx + 2] = v.z;
            tile[ty][4 * tx + 3] = v.w;
        }
    }
    __syncthreads();
    // store: rows = c, 128-bit along L
    {
        int lbase = l0 + 4 * tx;
        if (lbase + 3 < L_) {
            float4 v = make_float4(tile[4 * tx + 0][ty], tile[4 * tx + 1][ty],
                                   tile[4 * tx + 2][ty], tile[4 * tx + 3][ty]);
            *(float4*)&g_xT[((size_t)b * C_ + c0 + ty) * L_ + lbase] = v;
        }
    }
}

// ---------------- Kernel D: resT (B,C,L) -> out res region (B,L,C), 128-bit both sides ----------------
__global__ void k_transpose_res(float* __restrict__ out) {
    __shared__ float tile[32][33];
    int b = blockIdx.z;
    int l0 = blockIdx.x * 32, c0 = blockIdx.y * 32;
    int tx = threadIdx.x, ty = threadIdx.y;
    // load: rows = c, 128-bit along L
    {
        int lbase = l0 + 4 * tx;
        if (lbase + 3 < L_) {
            float4 v = *(const float4*)&g_resT[((size_t)b * C_ + c0 + ty) * L_ + lbase];
            tile[4 * tx + 0][ty] = v.x;
            tile[4 * tx + 1][ty] = v.y;
            tile[4 * tx + 2][ty] = v.z;
            tile[4 * tx + 3][ty] = v.w;
        }
    }
    __syncthreads();
    // store: rows = l, 128-bit along C
    {
        int l = l0 + ty;
        if (l < L_) {
            float4 v = make_float4(tile[ty][4 * tx + 0], tile[ty][4 * tx + 1],
                                   tile[ty][4 * tx + 2], tile[ty][4 * tx + 3]);
            *(float4*)&out[((size_t)b * L_ + l) * C_ + c0 + 4 * tx] = v;
        }
    }
}

// ---------------- Kernel B: both branches, bx&1 selects; n = bx>>1 ----------------
__global__ __launch_bounds__(256, 4) void k_branches(
    const float* __restrict__ wq10, const float* __restrict__ bq10,
    const float* __restrict__ wk10, const float* __restrict__ bk10,
    const float* __restrict__ wl10, const float* __restrict__ bl10,
    const float* __restrict__ wq20, const float* __restrict__ bq20,
    const float* __restrict__ wk20, const float* __restrict__ bk20,
    const float* __restrict__ wl20, const float* __restrict__ bl20,
    float* __restrict__ out)
{
    int bx = blockIdx.x;
    int n = bx >> 1;
    int tid = threadIdx.x, lane = tid & 31, wid = tid >> 5;

    __shared__ float zs[L_];
    __shared__ float2 qb2[L_];     // q duplicated into both halves, pre-scaled by s*log2e
    __shared__ float kb[L_];
    __shared__ float wbuf[1300];   // branch-dependent weight staging
    __shared__ float bbuf[72];

    for (int i = tid; i < L_; i += 256) zs[i] = g_xT[(size_t)n * L_ + i];

    if ((bx & 1) == 0) {
        // =================== p = 10 branch ===================
        float* wqs = wbuf;          // 100
        float* wks = wbuf + 100;    // 100
        float* bqs = bbuf;          // 10
        float* bks = bbuf + 10;     // 10
        if (tid < 100) { wqs[tid] = wq10[tid]; wks[tid] = wk10[tid]; }
        if (tid >= 128 && tid < 138) {
            bqs[tid - 128] = bq10[tid - 128];
            bks[tid - 128] = bk10[tid - 128];
        }
        __syncthreads();

        const float s10 = rsqrtf(10.0f) * (float)M_LOG2E;   // fold log2e for ex2
        for (int e = tid; e < L_; e += 256) {
            int wi = e / 10, pi = e - wi * 10;
            unsigned long long aq = 0ull, ak = 0ull;
#pragma unroll
            for (int j = 0; j < 5; j++) {
                unsigned long long zz = *(const unsigned long long*)&zs[wi * 10 + 2 * j];
                aq = fma2(zz, *(const unsigned long long*)&wqs[pi * 10 + 2 * j], aq);
                ak = fma2(zz, *(const unsigned long long*)&wks[pi * 10 + 2 * j], ak);
            }
            float2 q2 = unpack2(aq), k2 = unpack2(ak);
            float qv = (bqs[pi] + q2.x + q2.y) * s10;
            qb2[e] = make_float2(qv, qv);
            kb[pi * 200 + wi] = bks[pi] + k2.x + k2.y;
        }
        __syncthreads();

        float* attn = out + A10_OFF + (size_t)n * 40000;
        const bool t1 = (lane < 18);              // cols 128 + 4*lane < 200
        for (int r0 = wid * 4; r0 < 200; r0 += 32) {
            unsigned long long a0[4][2], a1[4][2];
#pragma unroll
            for (int rr = 0; rr < 4; rr++) {
                a0[rr][0] = a0[rr][1] = 0ull;
                a1[rr][0] = a1[rr][1] = 0ull;
            }
#pragma unroll
            for (int pi = 0; pi < 10; pi++) {
                ulonglong2 kv0 = *(const ulonglong2*)&kb[pi * 200 + 4 * lane];
                ulonglong2 kv1 = make_ulonglong2(0ull, 0ull);
                if (t1) kv1 = *(const ulonglong2*)&kb[pi * 200 + 128 + 4 * lane];
#pragma unroll
                for (int rr = 0; rr < 4; rr++) {
                    unsigned long long qq = *(const unsigned long long*)&qb2[(r0 + rr) * 10 + pi];
                    a0[rr][0] = fma2(qq, kv0.x, a0[rr][0]);
                    a0[rr][1] = fma2(qq, kv0.y, a0[rr][1]);
                    a1[rr][0] = fma2(qq, kv1.x, a1[rr][0]);
                    a1[rr][1] = fma2(qq, kv1.y, a1[rr][1]);
                }
            }
#pragma unroll
            for (int rr = 0; rr < 4; rr++) {
                float2 v00 = unpack2(a0[rr][0]), v01 = unpack2(a0[rr][1]);
                float2 v10 = unpack2(a1[rr][0]), v11 = unpack2(a1[rr][1]);
                // no max subtraction: scores are O(10), ex2 cannot overflow fp32
                v00.x = ex2(v00.x); v00.y = ex2(v00.y);
                v01.x = ex2(v01.x); v01.y = ex2(v01.y);
                float part = v00.x + v00.y + v01.x + v01.y;
                if (t1) {
                    v10.x = ex2(v10.x); v10.y = ex2(v10.y);
                    v11.x = ex2(v11.x); v11.y = ex2(v11.y);
                    part += v10.x + v10.y + v11.x + v11.y;
                }
                float inv = frcp(warp_sum(part));
                float4 s0 = make_float4(v00.x * inv, v00.y * inv, v01.x * inv, v01.y * inv);
                __stcs((float4*)&attn[(size_t)(r0 + rr) * 200 + 4 * lane], s0);
                if (t1) {
                    float4 s1 = make_float4(v10.x * inv, v10.y * inv, v11.x * inv, v11.y * inv);
                    __stcs((float4*)&attn[(size_t)(r0 + rr) * 200 + 128 + 4 * lane], s1);
                }
            }
        }
    } else {
        // =================== p = 20 branch + res ===================
        float* wqs   = wbuf;           // 400
        float* wks   = wbuf + 400;     // 400
        float* wl20s = wbuf + 800;     // 400 (interp-folded)
        float* wl10s = wbuf + 1200;    // 100 (interp-folded)
        float* bqs   = bbuf;           // 20
        float* bks   = bbuf + 20;      // 20
        float* bl20s = bbuf + 40;      // 20
        float* bl10s = bbuf + 60;      // 10
        if (tid < 100) {
            int r = tid / 10, j = tid - r * 10;
            wl10s[tid] = 0.25f * (wl10[(20 * r + 9) * 10 + j] + wl10[(20 * r + 10) * 10 + j]);
        }
        for (int t = tid; t < 400; t += 256) {
            wqs[t] = wq20[t]; wks[t] = wk20[t];
            int r = t / 20, j = t - r * 20;
            wl20s[t] = 0.5f * wl20[(5 * r + 2) * 20 + j];
        }
        if (tid >= 128 && tid < 148) {
            int u = tid - 128;
            bqs[u] = bq20[u]; bks[u] = bk20[u];
            bl20s[u] = 0.5f * bl20[5 * u + 2];
            if (u < 10) bl10s[u] = 0.25f * (bl10[20 * u + 9] + bl10[20 * u + 10]);
        }
        __syncthreads();

        const float s20 = rsqrtf(20.0f) * (float)M_LOG2E;
        for (int e = tid; e < L_; e += 256) {
            int wi = e / 20, pi = e - wi * 20;
            unsigned long long aq = 0ull, ak = 0ull;
#pragma unroll
            for (int j = 0; j < 10; j++) {
                unsigned long long zz = *(const unsigned long long*)&zs[wi * 20 + 2 * j];
                aq = fma2(zz, *(const unsigned long long*)&wqs[pi * 20 + 2 * j], aq);
                ak = fma2(zz, *(const unsigned long long*)&wks[pi * 20 + 2 * j], ak);
            }
            float2 q2 = unpack2(aq), k2 = unpack2(ak);
            float qv = (bqs[pi] + q2.x + q2.y) * s20;
            qb2[e] = make_float2(qv, qv);
            kb[pi * 100 + wi] = bks[pi] + k2.x + k2.y;
        }

        // res = folded z2(p10) + folded z2(p20), written transposed
        for (int i = tid; i < L_; i += 256) {
            int a1i = i / 10, r1 = i - a1i * 10;
            unsigned long long acc1 = 0ull;
#pragma unroll
            for (int j = 0; j < 5; j++) {
                unsigned long long zz = *(const unsigned long long*)&zs[a1i * 10 + 2 * j];
                acc1 = fma2(zz, *(const unsigned long long*)&wl10s[r1 * 10 + 2 * j], acc1);
            }
            int a2i = i / 20, r2 = i - a2i * 20;
            unsigned long long acc2 = 0ull;
#pragma unroll
            for (int j = 0; j < 10; j++) {
                unsigned long long zz = *(const unsigned long long*)&zs[a2i * 20 + 2 * j];
                acc2 = fma2(zz, *(const unsigned long long*)&wl20s[r2 * 20 + 2 * j], acc2);
            }
            float2 u1 = unpack2(acc1), u2 = unpack2(acc2);
            g_resT[(size_t)n * L_ + i] = bl10s[r1] + bl20s[r2] + u1.x + u1.y + u2.x + u2.y;
        }
        __syncthreads();

        float* attn = out + A20_OFF + (size_t)n * 10000;
        const bool act = (lane < 25);
        for (int r0 = wid * 4; r0 < 100; r0 += 32) {
            unsigned long long a[4][2];
#pragma unroll
            for (int rr = 0; rr < 4; rr++) { a[rr][0] = a[rr][1] = 0ull; }
#pragma unroll
            for (int pi = 0; pi < 20; pi++) {
                ulonglong2 kv = make_ulonglong2(0ull, 0ull);
                if (act) kv = *(const ulonglong2*)&kb[pi * 100 + 4 * lane];
#pragma unroll
                for (int rr = 0; rr < 4; rr++) {
                    unsigned long long qq = *(const unsigned long long*)&qb2[(r0 + rr) * 20 + pi];
                    a[rr][0] = fma2(qq, kv.x, a[rr][0]);
                    a[rr][1] = fma2(qq, kv.y, a[rr][1]);
                }
            }
#pragma unroll
            for (int rr = 0; rr < 4; rr++) {
                float2 v0 = unpack2(a[rr][0]), v1 = unpack2(a[rr][1]);
                float part = 0.f;
                if (act) {
                    v0.x = ex2(v0.x); v0.y = ex2(v0.y);
                    v1.x = ex2(v1.x); v1.y = ex2(v1.y);
                    part = v0.x + v0.y + v1.x + v1.y;
                }
                float inv = frcp(warp_sum(part));
                if (act) {
                    float4 s = make_float4(v0.x * inv, v0.y * inv, v1.x * inv, v1.y * inv);
                    __stcs((float4*)&attn[(size_t)(r0 + rr) * 100 + 4 * lane], s);
                }
            }
        }
    }
}

extern "C" void kernel_launch(void* const* d_in, const int* in_sizes, int n_in,
                              void* d_out, int out_size) {
    const float* x    = (const float*)d_in[0];
    const float* wq10 = (const float*)d_in[1];
    const float* bq10 = (const float*)d_in[2];
    const float* wk10 = (const float*)d_in[3];
    const float* bk10 = (const float*)d_in[4];
    const float* wl10 = (const float*)d_in[5];
    const float* bl10 = (const float*)d_in[6];
    const float* wq20 = (const float*)d_in[7];
    const float* bq20 = (const float*)d_in[8];
    const float* wk20 = (const float*)d_in[9];
    const float* bk20 = (const float*)d_in[10];
    const float* wl20 = (const float*)d_in[11];
    const float* bl20 = (const float*)d_in[12];
    float* out = (float*)d_out;

    dim3 tb(8, 32);
    dim3 gt((L_ + 31) / 32, C_ / 32, B_);
    k_transpose_x<<<gt, tb>>>(x);
    k_branches<<<2 * N_, 256>>>(wq10, bq10, wk10, bk10, wl10, bl10,
                                wq20, bq20, wk20, bk20, wl20, bl20, out);
    k_transpose_res<<<gt, tb>>>(out);
}